// round 7
// baseline (speedup 1.0000x reference)
#include <cuda_runtime.h>
#include <cuda_bf16.h>
#include <math.h>
#include <stdint.h>

// Problem shape (fixed by the dataset)
#define NG 16384   // n_genes
#define NL 4096    // n_latent (softmax axis, GEMM-K)
#define DK 64      // d_k
#define NC 1024    // n_cells
#define OUT_ELEMS (NG * NC)

// ---------------------------------------------------------------------------
// bf16 hi/lo scratch (static device arrays: allocation-free scratch)
// ---------------------------------------------------------------------------
__device__ __nv_bfloat16 g_Phi[(size_t)NG * NL];   // 134 MB
__device__ __nv_bfloat16 g_Plo[(size_t)NG * NL];   // 134 MB
__device__ __nv_bfloat16 g_VhiT[(size_t)NC * NL];  // 8 MB   V^T hi  [n][k]
__device__ __nv_bfloat16 g_VloT[(size_t)NC * NL];  // 8 MB   V^T lo  [n][k]

__device__ __forceinline__ uint32_t smem_to_u32(const void* p) {
    uint32_t a;
    asm("{ .reg .u64 t; cvta.to.shared.u64 t, %1; cvt.u32.u64 %0, t; }" : "=r"(a) : "l"(p));
    return a;
}

// ---------------------------------------------------------------------------
// JAX threefry2x32 Gumbel noise, partitionable mode, key (0, 42)
// ---------------------------------------------------------------------------
__device__ __forceinline__ float gumbel_at(uint32_t e) {
    uint32_t x0 = 0u, x1 = e;
    const uint32_t ks1 = 42u;
    const uint32_t ks2 = 0x1BD11BDAu ^ 42u;
    x1 += ks1;
#define TFR(r) { x0 += x1; x1 = __funnelshift_l(x1, x1, (r)); x1 ^= x0; }
    TFR(13) TFR(15) TFR(26) TFR(6)
    x0 += ks1; x1 += ks2 + 1u;
    TFR(17) TFR(29) TFR(16) TFR(24)
    x0 += ks2; x1 += 2u;
    TFR(13) TFR(15) TFR(26) TFR(6)
    x1 += ks1 + 3u;
    TFR(17) TFR(29) TFR(16) TFR(24)
    x0 += ks1; x1 += ks2 + 4u;
    TFR(13) TFR(15) TFR(26) TFR(6)
    x0 += ks2; x1 += 5u;
#undef TFR
    uint32_t bits = x0 ^ x1;
    float f = __uint_as_float(0x3F800000u | (bits >> 9)) - 1.0f;
    // w = -log(u), u ~= f. t = 1 - f is EXACT in fp32 (24-bit grid).
    float t = 1.0f - f;
    // Series path (t < 0.105): -log(1-t) = t*(1 + t/2 + ... + t^6/7), rel err < 6e-8
    float poly = 1.0f / 7.0f;
    poly = fmaf(poly, t, 1.0f / 6.0f);
    poly = fmaf(poly, t, 0.2f);
    poly = fmaf(poly, t, 0.25f);
    poly = fmaf(poly, t, 1.0f / 3.0f);
    poly = fmaf(poly, t, 0.5f);
    poly = fmaf(poly, t, 1.0f);
    float w_ser = t * poly;
    // MUFU path (t >= 0.105 -> w >= 0.11, absolute MUFU error harmless)
    float w_muf = -__logf(f);
    float w = (t < 0.105f) ? w_ser : w_muf;
    w = (f > 0.0f) ? w : 87.33654475f;   // f==0 -> u = tiny = 2^-126
    return -__logf(w);
}

// ---------------------------------------------------------------------------
// Kernel A: S = (Q @ K^T)/8 + gumbel
// ---------------------------------------------------------------------------
__global__ __launch_bounds__(256)
void score_kernel(const float* __restrict__ Q, const float* __restrict__ Km,
                  float* __restrict__ S)
{
    __shared__ float As[16][132];
    __shared__ float Bs[16][132];
    const int bm = blockIdx.y, bn = blockIdx.x;
    const int tid = threadIdx.x;
    const int tx = tid & 15, ty = tid >> 4;

    float acc[8][8];
#pragma unroll
    for (int i = 0; i < 8; i++)
#pragma unroll
        for (int j = 0; j < 8; j++) acc[i][j] = 0.0f;

    for (int k0 = 0; k0 < DK; k0 += 16) {
#pragma unroll
        for (int p = 0; p < 2; p++) {
            int idx = tid * 2 + p;
            int row = idx >> 2;
            int c4  = idx & 3;
            float4 va = *(const float4*)(Q  + (size_t)(bm * 128 + row) * DK + k0 + c4 * 4);
            As[c4 * 4 + 0][row] = va.x; As[c4 * 4 + 1][row] = va.y;
            As[c4 * 4 + 2][row] = va.z; As[c4 * 4 + 3][row] = va.w;
            float4 vb = *(const float4*)(Km + (size_t)(bn * 128 + row) * DK + k0 + c4 * 4);
            Bs[c4 * 4 + 0][row] = vb.x; Bs[c4 * 4 + 1][row] = vb.y;
            Bs[c4 * 4 + 2][row] = vb.z; Bs[c4 * 4 + 3][row] = vb.w;
        }
        __syncthreads();
#pragma unroll
        for (int kk = 0; kk < 16; kk++) {
            float a[8], b[8];
            *(float4*)&a[0] = *(const float4*)&As[kk][ty * 8];
            *(float4*)&a[4] = *(const float4*)&As[kk][ty * 8 + 4];
            *(float4*)&b[0] = *(const float4*)&Bs[kk][tx * 8];
            *(float4*)&b[4] = *(const float4*)&Bs[kk][tx * 8 + 4];
#pragma unroll
            for (int i = 0; i < 8; i++)
#pragma unroll
                for (int j = 0; j < 8; j++)
                    acc[i][j] = fmaf(a[i], b[j], acc[i][j]);
        }
        __syncthreads();
    }

#pragma unroll
    for (int i = 0; i < 8; i++) {
        uint32_t m = bm * 128 + ty * 8 + i;
        uint32_t e0 = m * (uint32_t)NL + bn * 128 + tx * 8;
        float4 o0, o1;
        o0.x = acc[i][0] * 0.125f + gumbel_at(e0 + 0);
        o0.y = acc[i][1] * 0.125f + gumbel_at(e0 + 1);
        o0.z = acc[i][2] * 0.125f + gumbel_at(e0 + 2);
        o0.w = acc[i][3] * 0.125f + gumbel_at(e0 + 3);
        o1.x = acc[i][4] * 0.125f + gumbel_at(e0 + 4);
        o1.y = acc[i][5] * 0.125f + gumbel_at(e0 + 5);
        o1.z = acc[i][6] * 0.125f + gumbel_at(e0 + 6);
        o1.w = acc[i][7] * 0.125f + gumbel_at(e0 + 7);
        *(float4*)(S + e0)     = o0;
        *(float4*)(S + e0 + 4) = o1;
    }
}

// ---------------------------------------------------------------------------
// Kernel B: in-place row softmax + fused bf16 hi/lo split of P
// ---------------------------------------------------------------------------
__device__ __forceinline__ void split1(float x, __nv_bfloat16& h, __nv_bfloat16& l) {
    h = __float2bfloat16(x);
    l = __float2bfloat16(x - __bfloat162float(h));
}

__global__ __launch_bounds__(256)
void softmax_kernel(float* __restrict__ P)
{
    __shared__ float4 row4[NL / 4];
    __shared__ float red[8];
    const int r = blockIdx.x, t = threadIdx.x;
    float4* g = (float4*)(P + (size_t)r * NL);

    float mx = -INFINITY;
#pragma unroll
    for (int q = 0; q < 4; q++) {
        float4 v = g[t + 256 * q];
        row4[t + 256 * q] = v;
        mx = fmaxf(mx, fmaxf(fmaxf(v.x, v.y), fmaxf(v.z, v.w)));
    }
#pragma unroll
    for (int o = 16; o > 0; o >>= 1)
        mx = fmaxf(mx, __shfl_xor_sync(0xffffffffu, mx, o));
    if ((t & 31) == 0) red[t >> 5] = mx;
    __syncthreads();
    mx = red[0];
#pragma unroll
    for (int w = 1; w < 8; w++) mx = fmaxf(mx, red[w]);
    __syncthreads();

    float s = 0.0f;
#pragma unroll
    for (int q = 0; q < 4; q++) {
        float4 v = row4[t + 256 * q];
        v.x = __expf(v.x - mx); v.y = __expf(v.y - mx);
        v.z = __expf(v.z - mx); v.w = __expf(v.w - mx);
        row4[t + 256 * q] = v;
        s += (v.x + v.y) + (v.z + v.w);
    }
#pragma unroll
    for (int o = 16; o > 0; o >>= 1)
        s += __shfl_xor_sync(0xffffffffu, s, o);
    if ((t & 31) == 0) red[t >> 5] = s;
    __syncthreads();
    float tot = red[0];
#pragma unroll
    for (int w = 1; w < 8; w++) tot += red[w];
    float inv = 1.0f / tot;
    __syncthreads();

    uint2* ph = (uint2*)(g_Phi + (size_t)r * NL);
    uint2* pl = (uint2*)(g_Plo + (size_t)r * NL);
#pragma unroll
    for (int q = 0; q < 4; q++) {
        float4 v = row4[t + 256 * q];
        v.x *= inv; v.y *= inv; v.z *= inv; v.w *= inv;
        g[t + 256 * q] = v;
        __nv_bfloat16 hx, hy, hz, hw, lx, ly, lz, lw;
        split1(v.x, hx, lx); split1(v.y, hy, ly);
        split1(v.z, hz, lz); split1(v.w, hw, lw);
        __nv_bfloat162 h01 = __nv_bfloat162(hx, hy), h23 = __nv_bfloat162(hz, hw);
        __nv_bfloat162 l01 = __nv_bfloat162(lx, ly), l23 = __nv_bfloat162(lz, lw);
        uint2 hv, lv;
        hv.x = *(uint32_t*)&h01; hv.y = *(uint32_t*)&h23;
        lv.x = *(uint32_t*)&l01; lv.y = *(uint32_t*)&l23;
        ph[t + 256 * q] = hv;
        pl[t + 256 * q] = lv;
    }
}

// ---------------------------------------------------------------------------
// Kernel B2: transpose + bf16-split V:  V[k][n] -> V^T hi/lo [n][k]
// ---------------------------------------------------------------------------
__global__ __launch_bounds__(256)
void vsplit_kernel(const float* __restrict__ V)
{
    __shared__ float tile[32][33];
    const int n0 = blockIdx.x * 32, k0 = blockIdx.y * 32;
    const int tx = threadIdx.x & 31, ty = threadIdx.x >> 5;   // 32 x 8
#pragma unroll
    for (int i = 0; i < 32; i += 8)
        tile[ty + i][tx] = V[(size_t)(k0 + ty + i) * NC + n0 + tx];
    __syncthreads();
#pragma unroll
    for (int i = 0; i < 32; i += 8) {
        float f = tile[tx][ty + i];            // = V[k0+tx][n0+ty+i]
        __nv_bfloat16 h, l;
        split1(f, h, l);
        size_t o = (size_t)(n0 + ty + i) * NL + k0 + tx;
        g_VhiT[o] = h;
        g_VloT[o] = l;
    }
}

// ---------------------------------------------------------------------------
// Kernel C: out = P @ V, bf16 mma.sync 3-product, 4-stage cp.async pipeline.
// BK=16 per chunk, prefetch distance 3 (one empty commit per tail iter keeps
// the wait_group arithmetic uniform). CTA 128x128, 8 warps, warp tile 64x32.
// ---------------------------------------------------------------------------
#define SP 24                     // smem row stride in bf16 (48 B, 16B-aligned)
#define ARR_BYTES (128 * SP * 2)  // 6144 B per array per stage
#define STAGE_BYTES (4 * ARR_BYTES)   // 24576 B
#define NSTAGE 4
#define PV_SMEM (NSTAGE * STAGE_BYTES) // 98304 B

__device__ __forceinline__ void ldsm4(uint32_t* r, uint32_t addr) {
    asm volatile("ldmatrix.sync.aligned.m8n8.x4.shared.b16 {%0,%1,%2,%3}, [%4];"
                 : "=r"(r[0]), "=r"(r[1]), "=r"(r[2]), "=r"(r[3]) : "r"(addr));
}
__device__ __forceinline__ void mma_bf16(float* c, const uint32_t* a,
                                         uint32_t b0, uint32_t b1) {
    asm volatile("mma.sync.aligned.m16n8k16.row.col.f32.bf16.bf16.f32 "
                 "{%0,%1,%2,%3}, {%4,%5,%6,%7}, {%8,%9}, {%0,%1,%2,%3};"
                 : "+f"(c[0]), "+f"(c[1]), "+f"(c[2]), "+f"(c[3])
                 : "r"(a[0]), "r"(a[1]), "r"(a[2]), "r"(a[3]), "r"(b0), "r"(b1));
}
__device__ __forceinline__ void cpa16(uint32_t dst, const void* src) {
    asm volatile("cp.async.cg.shared.global [%0], [%1], 16;" :: "r"(dst), "l"(src));
}
#define CP_COMMIT() asm volatile("cp.async.commit_group;" ::: "memory")
#define CP_WAIT2()  asm volatile("cp.async.wait_group 2;" ::: "memory")

__global__ __launch_bounds__(256, 2)
void pv_kernel(float* __restrict__ O)
{
    extern __shared__ __align__(16) char dsm[];
    const uint32_t sbase = smem_to_u32(dsm);

    const int tid = threadIdx.x;
    const int lane = tid & 31, wid = tid >> 5;
    const int wm = wid >> 2, wn = wid & 3;           // warp grid 2 x 4
    const int bn = blockIdx.x, bm = blockIdx.y;

    const __nv_bfloat16* srcs[4] = {
        g_Phi  + (size_t)(bm * 128) * NL,
        g_Plo  + (size_t)(bm * 128) * NL,
        g_VhiT + (size_t)(bn * 128) * NL,
        g_VloT + (size_t)(bn * 128) * NL
    };

    float acc[4][4][4];
#pragma unroll
    for (int i = 0; i < 4; i++)
#pragma unroll
        for (int j = 0; j < 4; j++)
#pragma unroll
            for (int q = 0; q < 4; q++) acc[i][j][q] = 0.0f;

    const int lrow = (lane & 7) + ((lane >> 3) & 1) * 8;   // 0..15
    const int lcol8 = (lane >> 4) * 8;                     // 0 or 8
    // per-thread load mapping for one 16-K chunk: row = tid>>1, half = tid&1
    const int ldrow = tid >> 1, ldkc = tid & 1;

    auto load_stage = [&](int st, int k0) {
        uint32_t stb = sbase + st * STAGE_BYTES;
        uint32_t dst = stb + (ldrow * SP + ldkc * 8) * 2;
        size_t   gof = (size_t)ldrow * NL + k0 + ldkc * 8;
#pragma unroll
        for (int a = 0; a < 4; a++)
            cpa16(dst + a * ARR_BYTES, srcs[a] + gof);
    };

    load_stage(0, 0);  CP_COMMIT();
    load_stage(1, 16); CP_COMMIT();
    load_stage(2, 32); CP_COMMIT();

    const int NCH = NL / 16;   // 256 chunks
    for (int c = 0; c < NCH; c++) {
        CP_WAIT2();            // exactly 3 groups pending at this point -> stage c done
        __syncthreads();       // reads of buffer (c+3)&3 (chunk c-1) complete
        if (c + 3 < NCH) load_stage((c + 3) & (NSTAGE - 1), (c + 3) * 16);
        CP_COMMIT();           // commit (possibly empty) group: keeps count uniform

        const uint32_t stb = sbase + (c & (NSTAGE - 1)) * STAGE_BYTES;
        const uint32_t uPhi = stb, uPlo = stb + ARR_BYTES;
        const uint32_t uVhi = stb + 2 * ARR_BYTES, uVlo = stb + 3 * ARR_BYTES;

        const uint32_t aoff = ((wm * 64 + lrow) * SP + lcol8) * 2;
        const uint32_t boff = ((wn * 32 + lrow) * SP + lcol8) * 2;
        uint32_t ah[4][4], al[4][4];
#pragma unroll
        for (int mt = 0; mt < 4; mt++) {
            ldsm4(ah[mt], uPhi + aoff + mt * (16 * SP * 2));
            ldsm4(al[mt], uPlo + aoff + mt * (16 * SP * 2));
        }
        uint32_t bh[2][4], bl[2][4];
#pragma unroll
        for (int np = 0; np < 2; np++) {
            ldsm4(bh[np], uVhi + boff + np * (16 * SP * 2));
            ldsm4(bl[np], uVlo + boff + np * (16 * SP * 2));
        }
#pragma unroll
        for (int mt = 0; mt < 4; mt++)
#pragma unroll
            for (int nt = 0; nt < 4; nt++) {
                const int np = nt >> 1, sel = nt & 1;
                mma_bf16(acc[mt][nt], ah[mt], bh[np][sel], bh[np][sel + 2]);
                mma_bf16(acc[mt][nt], ah[mt], bl[np][sel], bl[np][sel + 2]);
                mma_bf16(acc[mt][nt], al[mt], bh[np][sel], bh[np][sel + 2]);
            }
    }

    // Epilogue
#pragma unroll
    for (int mt = 0; mt < 4; mt++) {
        int m = bm * 128 + wm * 64 + mt * 16 + (lane >> 2);
#pragma unroll
        for (int nt = 0; nt < 4; nt++) {
            int col = bn * 128 + wn * 32 + nt * 8 + 2 * (lane & 3);
            float2 v0 = make_float2(acc[mt][nt][0], acc[mt][nt][1]);
            float2 v1 = make_float2(acc[mt][nt][2], acc[mt][nt][3]);
            *(float2*)(O + (size_t)m * NC + col)       = v0;
            *(float2*)(O + (size_t)(m + 8) * NC + col) = v1;
        }
    }
}

// ---------------------------------------------------------------------------
// Launch
// ---------------------------------------------------------------------------
extern "C" void kernel_launch(void* const* d_in, const int* in_sizes, int n_in,
                              void* d_out, int out_size) {
    const float* Q  = (const float*)d_in[0];   // [16384, 64]
    const float* Km = (const float*)d_in[1];   // [4096, 64]
    const float* V  = (const float*)d_in[2];   // [4096, 1024]
    float* out = (float*)d_out;                // [16384, 1024]
    float* P   = out + OUT_ELEMS;              // [16384, 4096] p_attn

    static bool attr_done = false;
    if (!attr_done) {
        cudaFuncSetAttribute(pv_kernel, cudaFuncAttributeMaxDynamicSharedMemorySize,
                             PV_SMEM);
        attr_done = true;
    }

    dim3 gA(NL / 128, NG / 128);
    score_kernel<<<gA, 256>>>(Q, Km, P);

    vsplit_kernel<<<dim3(NC / 32, NL / 32), 256>>>(V);

    softmax_kernel<<<NG, 256>>>(P);

    dim3 gC(NC / 128, NG / 128);               // 8 x 128
    pv_kernel<<<gC, 256, PV_SMEM>>>(out);
}

// round 8
// speedup vs baseline: 1.2968x; 1.2968x over previous
#include <cuda_runtime.h>
#include <cuda_bf16.h>
#include <cuda_fp16.h>
#include <math.h>
#include <stdint.h>

// Problem shape (fixed by the dataset)
#define NG 16384   // n_genes
#define NL 4096    // n_latent (softmax axis, GEMM-K)
#define DK 64      // d_k
#define NC 1024    // n_cells
#define OUT_ELEMS (NG * NC)
#define PSCALE 1024.0f
#define INV_PSCALE (1.0f / 1024.0f)

// ---------------------------------------------------------------------------
// fp16 hi/lo scratch (static device arrays: allocation-free scratch)
// P is stored scaled by 1024 to keep lo parts out of subnormal territory.
// ---------------------------------------------------------------------------
__device__ __half g_Phi[(size_t)NG * NL];   // 134 MB  (P*1024) hi
__device__ __half g_Plo[(size_t)NG * NL];   // 134 MB  (P*1024) lo
__device__ __half g_VhT[(size_t)NC * NL];   // 8 MB    V^T fp16  [n][k]

__device__ __forceinline__ uint32_t smem_to_u32(const void* p) {
    uint32_t a;
    asm("{ .reg .u64 t; cvta.to.shared.u64 t, %1; cvt.u32.u64 %0, t; }" : "=r"(a) : "l"(p));
    return a;
}

// ---------------------------------------------------------------------------
// JAX threefry2x32 Gumbel noise, partitionable mode, key (0, 42)
// ---------------------------------------------------------------------------
__device__ __forceinline__ float gumbel_at(uint32_t e) {
    uint32_t x0 = 0u, x1 = e;
    const uint32_t ks1 = 42u;
    const uint32_t ks2 = 0x1BD11BDAu ^ 42u;
    x1 += ks1;
#define TFR(r) { x0 += x1; x1 = __funnelshift_l(x1, x1, (r)); x1 ^= x0; }
    TFR(13) TFR(15) TFR(26) TFR(6)
    x0 += ks1; x1 += ks2 + 1u;
    TFR(17) TFR(29) TFR(16) TFR(24)
    x0 += ks2; x1 += 2u;
    TFR(13) TFR(15) TFR(26) TFR(6)
    x1 += ks1 + 3u;
    TFR(17) TFR(29) TFR(16) TFR(24)
    x0 += ks1; x1 += ks2 + 4u;
    TFR(13) TFR(15) TFR(26) TFR(6)
    x0 += ks2; x1 += 5u;
#undef TFR
    uint32_t bits = x0 ^ x1;
    float f = __uint_as_float(0x3F800000u | (bits >> 9)) - 1.0f;
    // w = -log(u), u ~= f. t = 1 - f is EXACT in fp32 (24-bit grid).
    float t = 1.0f - f;
    float poly = 1.0f / 7.0f;
    poly = fmaf(poly, t, 1.0f / 6.0f);
    poly = fmaf(poly, t, 0.2f);
    poly = fmaf(poly, t, 0.25f);
    poly = fmaf(poly, t, 1.0f / 3.0f);
    poly = fmaf(poly, t, 0.5f);
    poly = fmaf(poly, t, 1.0f);
    float w_ser = t * poly;
    float w_muf = -__logf(f);
    float w = (t < 0.105f) ? w_ser : w_muf;
    w = (f > 0.0f) ? w : 87.33654475f;   // f==0 -> u = tiny = 2^-126
    return -__logf(w);
}

// ---------------------------------------------------------------------------
// Kernel A: S = (Q @ K^T)/8 + gumbel
// ---------------------------------------------------------------------------
__global__ __launch_bounds__(256)
void score_kernel(const float* __restrict__ Q, const float* __restrict__ Km,
                  float* __restrict__ S)
{
    __shared__ float As[16][132];
    __shared__ float Bs[16][132];
    const int bm = blockIdx.y, bn = blockIdx.x;
    const int tid = threadIdx.x;
    const int tx = tid & 15, ty = tid >> 4;

    float acc[8][8];
#pragma unroll
    for (int i = 0; i < 8; i++)
#pragma unroll
        for (int j = 0; j < 8; j++) acc[i][j] = 0.0f;

    for (int k0 = 0; k0 < DK; k0 += 16) {
#pragma unroll
        for (int p = 0; p < 2; p++) {
            int idx = tid * 2 + p;
            int row = idx >> 2;
            int c4  = idx & 3;
            float4 va = *(const float4*)(Q  + (size_t)(bm * 128 + row) * DK + k0 + c4 * 4);
            As[c4 * 4 + 0][row] = va.x; As[c4 * 4 + 1][row] = va.y;
            As[c4 * 4 + 2][row] = va.z; As[c4 * 4 + 3][row] = va.w;
            float4 vb = *(const float4*)(Km + (size_t)(bn * 128 + row) * DK + k0 + c4 * 4);
            Bs[c4 * 4 + 0][row] = vb.x; Bs[c4 * 4 + 1][row] = vb.y;
            Bs[c4 * 4 + 2][row] = vb.z; Bs[c4 * 4 + 3][row] = vb.w;
        }
        __syncthreads();
#pragma unroll
        for (int kk = 0; kk < 16; kk++) {
            float a[8], b[8];
            *(float4*)&a[0] = *(const float4*)&As[kk][ty * 8];
            *(float4*)&a[4] = *(const float4*)&As[kk][ty * 8 + 4];
            *(float4*)&b[0] = *(const float4*)&Bs[kk][tx * 8];
            *(float4*)&b[4] = *(const float4*)&Bs[kk][tx * 8 + 4];
#pragma unroll
            for (int i = 0; i < 8; i++)
#pragma unroll
                for (int j = 0; j < 8; j++)
                    acc[i][j] = fmaf(a[i], b[j], acc[i][j]);
        }
        __syncthreads();
    }

#pragma unroll
    for (int i = 0; i < 8; i++) {
        uint32_t m = bm * 128 + ty * 8 + i;
        uint32_t e0 = m * (uint32_t)NL + bn * 128 + tx * 8;
        float4 o0, o1;
        o0.x = acc[i][0] * 0.125f + gumbel_at(e0 + 0);
        o0.y = acc[i][1] * 0.125f + gumbel_at(e0 + 1);
        o0.z = acc[i][2] * 0.125f + gumbel_at(e0 + 2);
        o0.w = acc[i][3] * 0.125f + gumbel_at(e0 + 3);
        o1.x = acc[i][4] * 0.125f + gumbel_at(e0 + 4);
        o1.y = acc[i][5] * 0.125f + gumbel_at(e0 + 5);
        o1.z = acc[i][6] * 0.125f + gumbel_at(e0 + 6);
        o1.w = acc[i][7] * 0.125f + gumbel_at(e0 + 7);
        *(float4*)(S + e0)     = o0;
        *(float4*)(S + e0 + 4) = o1;
    }
}

// ---------------------------------------------------------------------------
// Kernel B: in-place row softmax + fused fp16 hi/lo split of P (scaled x1024)
// ---------------------------------------------------------------------------
__device__ __forceinline__ void split1h(float x, __half& h, __half& l) {
    float xs = x * PSCALE;
    h = __float2half_rn(xs);
    l = __float2half_rn(xs - __half2float(h));
}

__global__ __launch_bounds__(256)
void softmax_kernel(float* __restrict__ P)
{
    __shared__ float4 row4[NL / 4];
    __shared__ float red[8];
    const int r = blockIdx.x, t = threadIdx.x;
    float4* g = (float4*)(P + (size_t)r * NL);

    float mx = -INFINITY;
#pragma unroll
    for (int q = 0; q < 4; q++) {
        float4 v = g[t + 256 * q];
        row4[t + 256 * q] = v;
        mx = fmaxf(mx, fmaxf(fmaxf(v.x, v.y), fmaxf(v.z, v.w)));
    }
#pragma unroll
    for (int o = 16; o > 0; o >>= 1)
        mx = fmaxf(mx, __shfl_xor_sync(0xffffffffu, mx, o));
    if ((t & 31) == 0) red[t >> 5] = mx;
    __syncthreads();
    mx = red[0];
#pragma unroll
    for (int w = 1; w < 8; w++) mx = fmaxf(mx, red[w]);
    __syncthreads();

    float s = 0.0f;
#pragma unroll
    for (int q = 0; q < 4; q++) {
        float4 v = row4[t + 256 * q];
        v.x = __expf(v.x - mx); v.y = __expf(v.y - mx);
        v.z = __expf(v.z - mx); v.w = __expf(v.w - mx);
        row4[t + 256 * q] = v;
        s += (v.x + v.y) + (v.z + v.w);
    }
#pragma unroll
    for (int o = 16; o > 0; o >>= 1)
        s += __shfl_xor_sync(0xffffffffu, s, o);
    if ((t & 31) == 0) red[t >> 5] = s;
    __syncthreads();
    float tot = red[0];
#pragma unroll
    for (int w = 1; w < 8; w++) tot += red[w];
    float inv = 1.0f / tot;
    __syncthreads();

    uint2* ph = (uint2*)(g_Phi + (size_t)r * NL);
    uint2* pl = (uint2*)(g_Plo + (size_t)r * NL);
#pragma unroll
    for (int q = 0; q < 4; q++) {
        float4 v = row4[t + 256 * q];
        v.x *= inv; v.y *= inv; v.z *= inv; v.w *= inv;
        g[t + 256 * q] = v;
        __half hx, hy, hz, hw, lx, ly, lz, lw;
        split1h(v.x, hx, lx); split1h(v.y, hy, ly);
        split1h(v.z, hz, lz); split1h(v.w, hw, lw);
        __half2 h01 = __halves2half2(hx, hy), h23 = __halves2half2(hz, hw);
        __half2 l01 = __halves2half2(lx, ly), l23 = __halves2half2(lz, lw);
        uint2 hv, lv;
        hv.x = *(uint32_t*)&h01; hv.y = *(uint32_t*)&h23;
        lv.x = *(uint32_t*)&l01; lv.y = *(uint32_t*)&l23;
        ph[t + 256 * q] = hv;
        pl[t + 256 * q] = lv;
    }
}

// ---------------------------------------------------------------------------
// Kernel B2: transpose V to fp16:  V[k][n] -> V^T fp16 [n][k]
// ---------------------------------------------------------------------------
__global__ __launch_bounds__(256)
void vsplit_kernel(const float* __restrict__ V)
{
    __shared__ float tile[32][33];
    const int n0 = blockIdx.x * 32, k0 = blockIdx.y * 32;
    const int tx = threadIdx.x & 31, ty = threadIdx.x >> 5;   // 32 x 8
#pragma unroll
    for (int i = 0; i < 32; i += 8)
        tile[ty + i][tx] = V[(size_t)(k0 + ty + i) * NC + n0 + tx];
    __syncthreads();
#pragma unroll
    for (int i = 0; i < 32; i += 8) {
        float f = tile[tx][ty + i];            // = V[k0+tx][n0+ty+i]
        g_VhT[(size_t)(n0 + ty + i) * NL + k0 + tx] = __float2half_rn(f);
    }
}

// ---------------------------------------------------------------------------
// Kernel C: out = P @ V, fp16 mma.sync 2-product (Ph*Vh + Pl*Vh), fp32 accum.
// CTA 128x128, 8 warps (2x4), warp tile 64x32, BK=32, 3-stage cp.async ring.
// ---------------------------------------------------------------------------
#define SP 40                     // smem row stride in fp16 (80B)
#define ARR_BYTES (128 * SP * 2)  // 10240 B per array per stage
#define STAGE_BYTES (3 * ARR_BYTES)   // 30720 B (Phi, Plo, Vh)
#define NSTAGE 3
#define PV_SMEM (NSTAGE * STAGE_BYTES) // 92160 B

__device__ __forceinline__ void ldsm4(uint32_t* r, uint32_t addr) {
    asm volatile("ldmatrix.sync.aligned.m8n8.x4.shared.b16 {%0,%1,%2,%3}, [%4];"
                 : "=r"(r[0]), "=r"(r[1]), "=r"(r[2]), "=r"(r[3]) : "r"(addr));
}
__device__ __forceinline__ void mma_f16(float* c, const uint32_t* a,
                                        uint32_t b0, uint32_t b1) {
    asm volatile("mma.sync.aligned.m16n8k16.row.col.f32.f16.f16.f32 "
                 "{%0,%1,%2,%3}, {%4,%5,%6,%7}, {%8,%9}, {%0,%1,%2,%3};"
                 : "+f"(c[0]), "+f"(c[1]), "+f"(c[2]), "+f"(c[3])
                 : "r"(a[0]), "r"(a[1]), "r"(a[2]), "r"(a[3]), "r"(b0), "r"(b1));
}
__device__ __forceinline__ void cpa16(uint32_t dst, const void* src) {
    asm volatile("cp.async.cg.shared.global [%0], [%1], 16;" :: "r"(dst), "l"(src));
}
#define CP_COMMIT() asm volatile("cp.async.commit_group;" ::: "memory")
#define CP_WAIT1()  asm volatile("cp.async.wait_group 1;" ::: "memory")

__global__ __launch_bounds__(256, 2)
void pv_kernel(float* __restrict__ O)
{
    extern __shared__ __align__(16) char dsm[];
    const uint32_t sbase = smem_to_u32(dsm);

    const int tid = threadIdx.x;
    const int lane = tid & 31, wid = tid >> 5;
    const int wm = wid >> 2, wn = wid & 3;           // warp grid 2 x 4
    const int bn = blockIdx.x, bm = blockIdx.y;

    const __half* srcs[3] = {
        g_Phi + (size_t)(bm * 128) * NL,
        g_Plo + (size_t)(bm * 128) * NL,
        g_VhT + (size_t)(bn * 128) * NL
    };

    float acc[4][4][4];
#pragma unroll
    for (int i = 0; i < 4; i++)
#pragma unroll
        for (int j = 0; j < 4; j++)
#pragma unroll
            for (int q = 0; q < 4; q++) acc[i][j][q] = 0.0f;

    const int lrow = (lane & 7) + ((lane >> 3) & 1) * 8;   // 0..15
    const int lcol8 = (lane >> 4) * 8;                     // 0 or 8

    auto load_stage = [&](int st, int k0) {
        uint32_t stb = sbase + st * STAGE_BYTES;
#pragma unroll
        for (int a = 0; a < 3; a++)
#pragma unroll
            for (int u = 0; u < 2; u++) {
                int idx = tid + 256 * u;           // 0..511: 128 rows x 4 kc
                int row = idx >> 2, kc = idx & 3;
                uint32_t dst = stb + a * ARR_BYTES + (row * SP + kc * 8) * 2;
                cpa16(dst, srcs[a] + (size_t)row * NL + k0 + kc * 8);
            }
    };

    load_stage(0, 0);  CP_COMMIT();
    load_stage(1, 32); CP_COMMIT();

    const int NCH = NL / 32;   // 128 chunks
    for (int c = 0; c < NCH; c++) {
        CP_WAIT1();            // 2 groups pending -> stage c complete
        __syncthreads();       // reads of stage (c+2)%3 (chunk c-1) complete
        if (c + 2 < NCH) load_stage((c + 2) % NSTAGE, (c + 2) * 32);
        CP_COMMIT();           // uniform commit (possibly empty)

        const uint32_t stb = sbase + (c % NSTAGE) * STAGE_BYTES;
        const uint32_t uPhi = stb, uPlo = stb + ARR_BYTES, uVh = stb + 2 * ARR_BYTES;

#pragma unroll
        for (int kk = 0; kk < 32; kk += 16) {
            const uint32_t aoff = ((wm * 64 + lrow) * SP + kk + lcol8) * 2;
            const uint32_t boff = ((wn * 32 + lrow) * SP + kk + lcol8) * 2;
            uint32_t ah[4][4], al[4][4];
#pragma unroll
            for (int mt = 0; mt < 4; mt++) {
                ldsm4(ah[mt], uPhi + aoff + mt * (16 * SP * 2));
                ldsm4(al[mt], uPlo + aoff + mt * (16 * SP * 2));
            }
            uint32_t bh[2][4];
#pragma unroll
            for (int np = 0; np < 2; np++)
                ldsm4(bh[np], uVh + boff + np * (16 * SP * 2));
#pragma unroll
            for (int mt = 0; mt < 4; mt++)
#pragma unroll
                for (int nt = 0; nt < 4; nt++) {
                    const int np = nt >> 1, sel = nt & 1;
                    mma_f16(acc[mt][nt], ah[mt], bh[np][sel], bh[np][sel + 2]);
                    mma_f16(acc[mt][nt], al[mt], bh[np][sel], bh[np][sel + 2]);
                }
        }
    }

    // Epilogue (undo the 1024x P scaling)
#pragma unroll
    for (int mt = 0; mt < 4; mt++) {
        int m = bm * 128 + wm * 64 + mt * 16 + (lane >> 2);
#pragma unroll
        for (int nt = 0; nt < 4; nt++) {
            int col = bn * 128 + wn * 32 + nt * 8 + 2 * (lane & 3);
            float2 v0 = make_float2(acc[mt][nt][0] * INV_PSCALE,
                                    acc[mt][nt][1] * INV_PSCALE);
            float2 v1 = make_float2(acc[mt][nt][2] * INV_PSCALE,
                                    acc[mt][nt][3] * INV_PSCALE);
            *(float2*)(O + (size_t)m * NC + col)       = v0;
            *(float2*)(O + (size_t)(m + 8) * NC + col) = v1;
        }
    }
}

// ---------------------------------------------------------------------------
// Launch
// ---------------------------------------------------------------------------
extern "C" void kernel_launch(void* const* d_in, const int* in_sizes, int n_in,
                              void* d_out, int out_size) {
    const float* Q  = (const float*)d_in[0];   // [16384, 64]
    const float* Km = (const float*)d_in[1];   // [4096, 64]
    const float* V  = (const float*)d_in[2];   // [4096, 1024]
    float* out = (float*)d_out;                // [16384, 1024]
    float* P   = out + OUT_ELEMS;              // [16384, 4096] p_attn

    static bool attr_done = false;
    if (!attr_done) {
        cudaFuncSetAttribute(pv_kernel, cudaFuncAttributeMaxDynamicSharedMemorySize,
                             PV_SMEM);
        attr_done = true;
    }

    dim3 gA(NL / 128, NG / 128);
    score_kernel<<<gA, 256>>>(Q, Km, P);

    vsplit_kernel<<<dim3(NC / 32, NL / 32), 256>>>(V);

    softmax_kernel<<<NG, 256>>>(P);

    dim3 gC(NC / 128, NG / 128);               // 8 x 128
    pv_kernel<<<gC, 256, PV_SMEM>>>(out);
}

// round 9
// speedup vs baseline: 1.8564x; 1.4315x over previous
#include <cuda_runtime.h>
#include <cuda_bf16.h>
#include <cuda_fp16.h>
#include <math.h>
#include <stdint.h>

// Problem shape (fixed by the dataset)
#define NG 16384   // n_genes
#define NL 4096    // n_latent (softmax axis, GEMM-K)
#define DK 64      // d_k
#define NC 1024    // n_cells
#define OUT_ELEMS (NG * NC)
#define PSCALE 1024.0f
#define INV_PSCALE (1.0f / 1024.0f)

// ---------------------------------------------------------------------------
// fp16 scratch (static device arrays: allocation-free scratch)
// P is stored scaled by 1024 to keep small softmax weights out of fp16
// subnormal territory (flushed values correspond to p < 1e-7: negligible).
// ---------------------------------------------------------------------------
__device__ __half g_Ph[(size_t)NG * NL];    // 134 MB  fp16(P*1024)
__device__ __half g_VhT[(size_t)NC * NL];   // 8 MB    V^T fp16  [n][k]

__device__ __forceinline__ uint32_t smem_to_u32(const void* p) {
    uint32_t a;
    asm("{ .reg .u64 t; cvta.to.shared.u64 t, %1; cvt.u32.u64 %0, t; }" : "=r"(a) : "l"(p));
    return a;
}

// ---------------------------------------------------------------------------
// JAX threefry2x32 Gumbel noise, partitionable mode, key (0, 42)
// ---------------------------------------------------------------------------
__device__ __forceinline__ float gumbel_at(uint32_t e) {
    uint32_t x0 = 0u, x1 = e;
    const uint32_t ks1 = 42u;
    const uint32_t ks2 = 0x1BD11BDAu ^ 42u;
    x1 += ks1;
#define TFR(r) { x0 += x1; x1 = __funnelshift_l(x1, x1, (r)); x1 ^= x0; }
    TFR(13) TFR(15) TFR(26) TFR(6)
    x0 += ks1; x1 += ks2 + 1u;
    TFR(17) TFR(29) TFR(16) TFR(24)
    x0 += ks2; x1 += 2u;
    TFR(13) TFR(15) TFR(26) TFR(6)
    x1 += ks1 + 3u;
    TFR(17) TFR(29) TFR(16) TFR(24)
    x0 += ks1; x1 += ks2 + 4u;
    TFR(13) TFR(15) TFR(26) TFR(6)
    x0 += ks2; x1 += 5u;
#undef TFR
    uint32_t bits = x0 ^ x1;
    float f = __uint_as_float(0x3F800000u | (bits >> 9)) - 1.0f;
    // w = -log(u), u ~= f. t = 1 - f is EXACT in fp32 (24-bit grid).
    float t = 1.0f - f;
    float poly = 1.0f / 7.0f;
    poly = fmaf(poly, t, 1.0f / 6.0f);
    poly = fmaf(poly, t, 0.2f);
    poly = fmaf(poly, t, 0.25f);
    poly = fmaf(poly, t, 1.0f / 3.0f);
    poly = fmaf(poly, t, 0.5f);
    poly = fmaf(poly, t, 1.0f);
    float w_ser = t * poly;
    float w_muf = -__logf(f);
    float w = (t < 0.105f) ? w_ser : w_muf;
    w = (f > 0.0f) ? w : 87.33654475f;   // f==0 -> u = tiny = 2^-126
    return -__logf(w);
}

// ---------------------------------------------------------------------------
// Kernel A: S = (Q @ K^T)/8 + gumbel
// ---------------------------------------------------------------------------
__global__ __launch_bounds__(256)
void score_kernel(const float* __restrict__ Q, const float* __restrict__ Km,
                  float* __restrict__ S)
{
    __shared__ float As[16][132];
    __shared__ float Bs[16][132];
    const int bm = blockIdx.y, bn = blockIdx.x;
    const int tid = threadIdx.x;
    const int tx = tid & 15, ty = tid >> 4;

    float acc[8][8];
#pragma unroll
    for (int i = 0; i < 8; i++)
#pragma unroll
        for (int j = 0; j < 8; j++) acc[i][j] = 0.0f;

    for (int k0 = 0; k0 < DK; k0 += 16) {
#pragma unroll
        for (int p = 0; p < 2; p++) {
            int idx = tid * 2 + p;
            int row = idx >> 2;
            int c4  = idx & 3;
            float4 va = *(const float4*)(Q  + (size_t)(bm * 128 + row) * DK + k0 + c4 * 4);
            As[c4 * 4 + 0][row] = va.x; As[c4 * 4 + 1][row] = va.y;
            As[c4 * 4 + 2][row] = va.z; As[c4 * 4 + 3][row] = va.w;
            float4 vb = *(const float4*)(Km + (size_t)(bn * 128 + row) * DK + k0 + c4 * 4);
            Bs[c4 * 4 + 0][row] = vb.x; Bs[c4 * 4 + 1][row] = vb.y;
            Bs[c4 * 4 + 2][row] = vb.z; Bs[c4 * 4 + 3][row] = vb.w;
        }
        __syncthreads();
#pragma unroll
        for (int kk = 0; kk < 16; kk++) {
            float a[8], b[8];
            *(float4*)&a[0] = *(const float4*)&As[kk][ty * 8];
            *(float4*)&a[4] = *(const float4*)&As[kk][ty * 8 + 4];
            *(float4*)&b[0] = *(const float4*)&Bs[kk][tx * 8];
            *(float4*)&b[4] = *(const float4*)&Bs[kk][tx * 8 + 4];
#pragma unroll
            for (int i = 0; i < 8; i++)
#pragma unroll
                for (int j = 0; j < 8; j++)
                    acc[i][j] = fmaf(a[i], b[j], acc[i][j]);
        }
        __syncthreads();
    }

#pragma unroll
    for (int i = 0; i < 8; i++) {
        uint32_t m = bm * 128 + ty * 8 + i;
        uint32_t e0 = m * (uint32_t)NL + bn * 128 + tx * 8;
        float4 o0, o1;
        o0.x = acc[i][0] * 0.125f + gumbel_at(e0 + 0);
        o0.y = acc[i][1] * 0.125f + gumbel_at(e0 + 1);
        o0.z = acc[i][2] * 0.125f + gumbel_at(e0 + 2);
        o0.w = acc[i][3] * 0.125f + gumbel_at(e0 + 3);
        o1.x = acc[i][4] * 0.125f + gumbel_at(e0 + 4);
        o1.y = acc[i][5] * 0.125f + gumbel_at(e0 + 5);
        o1.z = acc[i][6] * 0.125f + gumbel_at(e0 + 6);
        o1.w = acc[i][7] * 0.125f + gumbel_at(e0 + 7);
        *(float4*)(S + e0)     = o0;
        *(float4*)(S + e0 + 4) = o1;
    }
}

// ---------------------------------------------------------------------------
// Kernel B: in-place row softmax + fused fp16 conversion of P (scaled x1024)
// ---------------------------------------------------------------------------
__global__ __launch_bounds__(256)
void softmax_kernel(float* __restrict__ P)
{
    __shared__ float4 row4[NL / 4];
    __shared__ float red[8];
    const int r = blockIdx.x, t = threadIdx.x;
    float4* g = (float4*)(P + (size_t)r * NL);

    float mx = -INFINITY;
#pragma unroll
    for (int q = 0; q < 4; q++) {
        float4 v = g[t + 256 * q];
        row4[t + 256 * q] = v;
        mx = fmaxf(mx, fmaxf(fmaxf(v.x, v.y), fmaxf(v.z, v.w)));
    }
#pragma unroll
    for (int o = 16; o > 0; o >>= 1)
        mx = fmaxf(mx, __shfl_xor_sync(0xffffffffu, mx, o));
    if ((t & 31) == 0) red[t >> 5] = mx;
    __syncthreads();
    mx = red[0];
#pragma unroll
    for (int w = 1; w < 8; w++) mx = fmaxf(mx, red[w]);
    __syncthreads();

    float s = 0.0f;
#pragma unroll
    for (int q = 0; q < 4; q++) {
        float4 v = row4[t + 256 * q];
        v.x = __expf(v.x - mx); v.y = __expf(v.y - mx);
        v.z = __expf(v.z - mx); v.w = __expf(v.w - mx);
        row4[t + 256 * q] = v;
        s += (v.x + v.y) + (v.z + v.w);
    }
#pragma unroll
    for (int o = 16; o > 0; o >>= 1)
        s += __shfl_xor_sync(0xffffffffu, s, o);
    if ((t & 31) == 0) red[t >> 5] = s;
    __syncthreads();
    float tot = red[0];
#pragma unroll
    for (int w = 1; w < 8; w++) tot += red[w];
    float inv = 1.0f / tot;
    float invs = inv * PSCALE;
    __syncthreads();

    uint2* ph = (uint2*)(g_Ph + (size_t)r * NL);
#pragma unroll
    for (int q = 0; q < 4; q++) {
        float4 v = row4[t + 256 * q];
        v.x *= inv; v.y *= inv; v.z *= inv; v.w *= inv;
        g[t + 256 * q] = v;
        // fp16(P * 1024): recompute from pre-normalized values for 1 mult
        __half2 h01 = __floats2half2_rn(v.x * PSCALE, v.y * PSCALE);
        __half2 h23 = __floats2half2_rn(v.z * PSCALE, v.w * PSCALE);
        uint2 hv;
        hv.x = *(uint32_t*)&h01; hv.y = *(uint32_t*)&h23;
        ph[t + 256 * q] = hv;
    }
    (void)invs;
}

// ---------------------------------------------------------------------------
// Kernel B2: transpose V to fp16:  V[k][n] -> V^T fp16 [n][k]
// ---------------------------------------------------------------------------
__global__ __launch_bounds__(256)
void vsplit_kernel(const float* __restrict__ V)
{
    __shared__ float tile[32][33];
    const int n0 = blockIdx.x * 32, k0 = blockIdx.y * 32;
    const int tx = threadIdx.x & 31, ty = threadIdx.x >> 5;   // 32 x 8
#pragma unroll
    for (int i = 0; i < 32; i += 8)
        tile[ty + i][tx] = V[(size_t)(k0 + ty + i) * NC + n0 + tx];
    __syncthreads();
#pragma unroll
    for (int i = 0; i < 32; i += 8) {
        float f = tile[tx][ty + i];            // = V[k0+tx][n0+ty+i]
        g_VhT[(size_t)(n0 + ty + i) * NL + k0 + tx] = __float2half_rn(f);
    }
}

// ---------------------------------------------------------------------------
// Kernel C: out = P @ V, fp16 mma.sync single product (Ph*Vh), fp32 accum.
// CTA 128x128, 8 warps (2x4), warp tile 64x32, BK=32, 3-stage cp.async ring.
// ---------------------------------------------------------------------------
#define SP 40                     // smem row stride in fp16 (80B)
#define ARR_BYTES (128 * SP * 2)  // 10240 B per array per stage
#define STAGE_BYTES (2 * ARR_BYTES)   // 20480 B (Ph, Vh)
#define NSTAGE 3
#define PV_SMEM (NSTAGE * STAGE_BYTES) // 61440 B

__device__ __forceinline__ void ldsm4(uint32_t* r, uint32_t addr) {
    asm volatile("ldmatrix.sync.aligned.m8n8.x4.shared.b16 {%0,%1,%2,%3}, [%4];"
                 : "=r"(r[0]), "=r"(r[1]), "=r"(r[2]), "=r"(r[3]) : "r"(addr));
}
__device__ __forceinline__ void mma_f16(float* c, const uint32_t* a,
                                        uint32_t b0, uint32_t b1) {
    asm volatile("mma.sync.aligned.m16n8k16.row.col.f32.f16.f16.f32 "
                 "{%0,%1,%2,%3}, {%4,%5,%6,%7}, {%8,%9}, {%0,%1,%2,%3};"
                 : "+f"(c[0]), "+f"(c[1]), "+f"(c[2]), "+f"(c[3])
                 : "r"(a[0]), "r"(a[1]), "r"(a[2]), "r"(a[3]), "r"(b0), "r"(b1));
}
__device__ __forceinline__ void cpa16(uint32_t dst, const void* src) {
    asm volatile("cp.async.cg.shared.global [%0], [%1], 16;" :: "r"(dst), "l"(src));
}
#define CP_COMMIT() asm volatile("cp.async.commit_group;" ::: "memory")
#define CP_WAIT1()  asm volatile("cp.async.wait_group 1;" ::: "memory")

__global__ __launch_bounds__(256, 2)
void pv_kernel(float* __restrict__ O)
{
    extern __shared__ __align__(16) char dsm[];
    const uint32_t sbase = smem_to_u32(dsm);

    const int tid = threadIdx.x;
    const int lane = tid & 31, wid = tid >> 5;
    const int wm = wid >> 2, wn = wid & 3;           // warp grid 2 x 4
    const int bn = blockIdx.x, bm = blockIdx.y;

    const __half* srcP = g_Ph  + (size_t)(bm * 128) * NL;
    const __half* srcV = g_VhT + (size_t)(bn * 128) * NL;

    float acc[4][4][4];
#pragma unroll
    for (int i = 0; i < 4; i++)
#pragma unroll
        for (int j = 0; j < 4; j++)
#pragma unroll
            for (int q = 0; q < 4; q++) acc[i][j][q] = 0.0f;

    const int lrow = (lane & 7) + ((lane >> 3) & 1) * 8;   // 0..15
    const int lcol8 = (lane >> 4) * 8;                     // 0 or 8

    auto load_stage = [&](int st, int k0) {
        uint32_t stb = sbase + st * STAGE_BYTES;
#pragma unroll
        for (int u = 0; u < 2; u++) {
            int idx = tid + 256 * u;           // 0..511: 128 rows x 4 kc
            int row = idx >> 2, kc = idx & 3;
            uint32_t so = (row * SP + kc * 8) * 2;
            size_t   go = (size_t)row * NL + k0 + kc * 8;
            cpa16(stb + so, srcP + go);
            cpa16(stb + ARR_BYTES + so, srcV + go);
        }
    };

    load_stage(0, 0);  CP_COMMIT();
    load_stage(1, 32); CP_COMMIT();

    const int NCH = NL / 32;   // 128 chunks
    for (int c = 0; c < NCH; c++) {
        CP_WAIT1();            // 2 groups pending -> stage c complete
        __syncthreads();       // reads of stage (c+2)%3 (chunk c-1) complete
        if (c + 2 < NCH) load_stage((c + 2) % NSTAGE, (c + 2) * 32);
        CP_COMMIT();           // uniform commit (possibly empty)

        const uint32_t stb = sbase + (c % NSTAGE) * STAGE_BYTES;
        const uint32_t uPh = stb, uVh = stb + ARR_BYTES;

#pragma unroll
        for (int kk = 0; kk < 32; kk += 16) {
            const uint32_t aoff = ((wm * 64 + lrow) * SP + kk + lcol8) * 2;
            const uint32_t boff = ((wn * 32 + lrow) * SP + kk + lcol8) * 2;
            uint32_t ah[4][4];
#pragma unroll
            for (int mt = 0; mt < 4; mt++)
                ldsm4(ah[mt], uPh + aoff + mt * (16 * SP * 2));
            uint32_t bh[2][4];
#pragma unroll
            for (int np = 0; np < 2; np++)
                ldsm4(bh[np], uVh + boff + np * (16 * SP * 2));
#pragma unroll
            for (int mt = 0; mt < 4; mt++)
#pragma unroll
                for (int nt = 0; nt < 4; nt++) {
                    const int np = nt >> 1, sel = nt & 1;
                    mma_f16(acc[mt][nt], ah[mt], bh[np][sel], bh[np][sel + 2]);
                }
        }
    }

    // Epilogue (undo the 1024x P scaling)
#pragma unroll
    for (int mt = 0; mt < 4; mt++) {
        int m = bm * 128 + wm * 64 + mt * 16 + (lane >> 2);
#pragma unroll
        for (int nt = 0; nt < 4; nt++) {
            int col = bn * 128 + wn * 32 + nt * 8 + 2 * (lane & 3);
            float2 v0 = make_float2(acc[mt][nt][0] * INV_PSCALE,
                                    acc[mt][nt][1] * INV_PSCALE);
            float2 v1 = make_float2(acc[mt][nt][2] * INV_PSCALE,
                                    acc[mt][nt][3] * INV_PSCALE);
            *(float2*)(O + (size_t)m * NC + col)       = v0;
            *(float2*)(O + (size_t)(m + 8) * NC + col) = v1;
        }
    }
}

// ---------------------------------------------------------------------------
// Launch
// ---------------------------------------------------------------------------
extern "C" void kernel_launch(void* const* d_in, const int* in_sizes, int n_in,
                              void* d_out, int out_size) {
    const float* Q  = (const float*)d_in[0];   // [16384, 64]
    const float* Km = (const float*)d_in[1];   // [4096, 64]
    const float* V  = (const float*)d_in[2];   // [4096, 1024]
    float* out = (float*)d_out;                // [16384, 1024]
    float* P   = out + OUT_ELEMS;              // [16384, 4096] p_attn

    static bool attr_done = false;
    if (!attr_done) {
        cudaFuncSetAttribute(pv_kernel, cudaFuncAttributeMaxDynamicSharedMemorySize,
                             PV_SMEM);
        attr_done = true;
    }

    dim3 gA(NL / 128, NG / 128);
    score_kernel<<<gA, 256>>>(Q, Km, P);

    vsplit_kernel<<<dim3(NC / 32, NL / 32), 256>>>(V);

    softmax_kernel<<<NG, 256>>>(P);

    dim3 gC(NC / 128, NG / 128);               // 8 x 128
    pv_kernel<<<gC, 256, PV_SMEM>>>(out);
}

// round 10
// speedup vs baseline: 2.1168x; 1.1403x over previous
#include <cuda_runtime.h>
#include <cuda_bf16.h>
#include <cuda_fp16.h>
#include <math.h>
#include <stdint.h>

// Problem shape (fixed by the dataset)
#define NG 16384   // n_genes
#define NL 4096    // n_latent (softmax axis, GEMM-K)
#define DK 64      // d_k
#define NC 1024    // n_cells
#define OUT_ELEMS (NG * NC)
#define PSCALE 1024.0f
#define INV_PSCALE (1.0f / 1024.0f)

__device__ __half g_Ph[(size_t)NG * NL];    // 134 MB  fp16(P*1024)
__device__ __half g_VhT[(size_t)NC * NL];   // 8 MB    V^T fp16  [n][k]

__device__ __forceinline__ uint32_t smem_to_u32(const void* p) {
    uint32_t a;
    asm("{ .reg .u64 t; cvta.to.shared.u64 t, %1; cvt.u32.u64 %0, t; }" : "=r"(a) : "l"(p));
    return a;
}
__device__ __forceinline__ void ldsm4(uint32_t* r, uint32_t addr) {
    asm volatile("ldmatrix.sync.aligned.m8n8.x4.shared.b16 {%0,%1,%2,%3}, [%4];"
                 : "=r"(r[0]), "=r"(r[1]), "=r"(r[2]), "=r"(r[3]) : "r"(addr));
}
__device__ __forceinline__ void mma_f16(float* c, const uint32_t* a,
                                        uint32_t b0, uint32_t b1) {
    asm volatile("mma.sync.aligned.m16n8k16.row.col.f32.f16.f16.f32 "
                 "{%0,%1,%2,%3}, {%4,%5,%6,%7}, {%8,%9}, {%0,%1,%2,%3};"
                 : "+f"(c[0]), "+f"(c[1]), "+f"(c[2]), "+f"(c[3])
                 : "r"(a[0]), "r"(a[1]), "r"(a[2]), "r"(a[3]), "r"(b0), "r"(b1));
}
__device__ __forceinline__ void cpa16(uint32_t dst, const void* src) {
    asm volatile("cp.async.cg.shared.global [%0], [%1], 16;" :: "r"(dst), "l"(src));
}
#define CP_COMMIT() asm volatile("cp.async.commit_group;" ::: "memory")
#define CP_WAIT1()  asm volatile("cp.async.wait_group 1;" ::: "memory")

// ---------------------------------------------------------------------------
// JAX threefry2x32 Gumbel noise, partitionable mode, key (0, 42)
// ---------------------------------------------------------------------------
__device__ __forceinline__ float gumbel_at(uint32_t e) {
    uint32_t x0 = 0u, x1 = e;
    const uint32_t ks1 = 42u;
    const uint32_t ks2 = 0x1BD11BDAu ^ 42u;
    x1 += ks1;
#define TFR(r) { x0 += x1; x1 = __funnelshift_l(x1, x1, (r)); x1 ^= x0; }
    TFR(13) TFR(15) TFR(26) TFR(6)
    x0 += ks1; x1 += ks2 + 1u;
    TFR(17) TFR(29) TFR(16) TFR(24)
    x0 += ks2; x1 += 2u;
    TFR(13) TFR(15) TFR(26) TFR(6)
    x1 += ks1 + 3u;
    TFR(17) TFR(29) TFR(16) TFR(24)
    x0 += ks1; x1 += ks2 + 4u;
    TFR(13) TFR(15) TFR(26) TFR(6)
    x0 += ks2; x1 += 5u;
#undef TFR
    uint32_t bits = x0 ^ x1;
    float f = __uint_as_float(0x3F800000u | (bits >> 9)) - 1.0f;
    float t = 1.0f - f;   // exact
    float poly = 1.0f / 7.0f;
    poly = fmaf(poly, t, 1.0f / 6.0f);
    poly = fmaf(poly, t, 0.2f);
    poly = fmaf(poly, t, 0.25f);
    poly = fmaf(poly, t, 1.0f / 3.0f);
    poly = fmaf(poly, t, 0.5f);
    poly = fmaf(poly, t, 1.0f);
    float w_ser = t * poly;
    float w_muf = -__logf(f);
    float w = (t < 0.105f) ? w_ser : w_muf;
    w = (f > 0.0f) ? w : 87.33654475f;
    return -__logf(w);
}

// ---------------------------------------------------------------------------
// Kernel A: S = (Q @ K^T)/8 + gumbel — fp16 hi/lo 3-product tensor GEMM.
// CTA 128x128 tile, 8 warps (2x4), warp 64x32, K=64 in one smem phase.
// ---------------------------------------------------------------------------
#define SSP 72                         // smem stride fp16 (144 B rows)
#define SC_ARR (128 * SSP * 2)         // 18432 B per array
#define SC_SMEM (4 * SC_ARR)           // 73728 B (Qhi,Qlo,Khi,Klo)

__global__ __launch_bounds__(256, 2)
void score_kernel(const float* __restrict__ Q, const float* __restrict__ Km,
                  float* __restrict__ S)
{
    extern __shared__ __align__(16) char ssm[];
    const uint32_t sb = smem_to_u32(ssm);
    const uint32_t uQh = sb, uQl = sb + SC_ARR, uKh = sb + 2 * SC_ARR, uKl = sb + 3 * SC_ARR;

    const int tid = threadIdx.x;
    const int lane = tid & 31, wid = tid >> 5;
    const int wm = wid >> 2, wn = wid & 3;
    const int bn = blockIdx.x, bm = blockIdx.y;

    // load + split Q,K tiles (each 128 rows x 64 fp32)
#pragma unroll
    for (int u = 0; u < 8; u++) {
        int idx = tid + 256 * u;        // 0..2047
        int row = idx >> 4, c4 = idx & 15;
        const float* src = (u < 4 ? Q + (size_t)(bm * 128 + row) * DK
                                  : Km + (size_t)(bn * 128 + (row & 127)) * DK);
        // u<4 covers Q rows 0..127 (idx 0..2047? no: u<4 -> idx<1024 -> row<64)
        (void)src;
    }
    // explicit two-tile load (Q: idx 0..2047, K: idx 0..2047)
#pragma unroll
    for (int u = 0; u < 8; u++) {
        int idx = tid + 256 * u;        // 0..2047: 128 rows x 16 c4
        int row = idx >> 4, c4 = idx & 15;
        float4 vq = *(const float4*)(Q + (size_t)(bm * 128 + row) * DK + c4 * 4);
        float4 vk = *(const float4*)(Km + (size_t)(bn * 128 + row) * DK + c4 * 4);
        uint32_t off = (row * SSP + c4 * 4) * 2;
        __half hx, hy, hz, hw;
        // Q hi/lo
        hx = __float2half_rn(vq.x); hy = __float2half_rn(vq.y);
        hz = __float2half_rn(vq.z); hw = __float2half_rn(vq.w);
        __half2 qh01 = __halves2half2(hx, hy), qh23 = __halves2half2(hz, hw);
        __half2 ql01 = __halves2half2(__float2half_rn(vq.x - __half2float(hx)),
                                      __float2half_rn(vq.y - __half2float(hy)));
        __half2 ql23 = __halves2half2(__float2half_rn(vq.z - __half2float(hz)),
                                      __float2half_rn(vq.w - __half2float(hw)));
        *(uint2*)(ssm + (uQh - sb) + off) = make_uint2(*(uint32_t*)&qh01, *(uint32_t*)&qh23);
        *(uint2*)(ssm + (uQl - sb) + off) = make_uint2(*(uint32_t*)&ql01, *(uint32_t*)&ql23);
        // K hi/lo
        hx = __float2half_rn(vk.x); hy = __float2half_rn(vk.y);
        hz = __float2half_rn(vk.z); hw = __float2half_rn(vk.w);
        __half2 kh01 = __halves2half2(hx, hy), kh23 = __halves2half2(hz, hw);
        __half2 kl01 = __halves2half2(__float2half_rn(vk.x - __half2float(hx)),
                                      __float2half_rn(vk.y - __half2float(hy)));
        __half2 kl23 = __halves2half2(__float2half_rn(vk.z - __half2float(hz)),
                                      __float2half_rn(vk.w - __half2float(hw)));
        *(uint2*)(ssm + (uKh - sb) + off) = make_uint2(*(uint32_t*)&kh01, *(uint32_t*)&kh23);
        *(uint2*)(ssm + (uKl - sb) + off) = make_uint2(*(uint32_t*)&kl01, *(uint32_t*)&kl23);
    }
    __syncthreads();

    float acc[4][4][4];
#pragma unroll
    for (int i = 0; i < 4; i++)
#pragma unroll
        for (int j = 0; j < 4; j++)
#pragma unroll
            for (int q = 0; q < 4; q++) acc[i][j][q] = 0.0f;

    const int lrow = (lane & 7) + ((lane >> 3) & 1) * 8;
    const int lcol8 = (lane >> 4) * 8;

#pragma unroll
    for (int kk = 0; kk < 64; kk += 16) {
        const uint32_t boff = ((wn * 32 + lrow) * SSP + kk + lcol8) * 2;
        uint32_t bh[2][4], bl[2][4];
#pragma unroll
        for (int np = 0; np < 2; np++) {
            ldsm4(bh[np], uKh + boff + np * (16 * SSP * 2));
            ldsm4(bl[np], uKl + boff + np * (16 * SSP * 2));
        }
        const uint32_t aoff = ((wm * 64 + lrow) * SSP + kk + lcol8) * 2;
#pragma unroll
        for (int mt = 0; mt < 4; mt++) {
            uint32_t ah[4], al[4];
            ldsm4(ah, uQh + aoff + mt * (16 * SSP * 2));
            ldsm4(al, uQl + aoff + mt * (16 * SSP * 2));
#pragma unroll
            for (int nt = 0; nt < 4; nt++) {
                const int np = nt >> 1, sel = nt & 1;
                mma_f16(acc[mt][nt], ah, bh[np][sel], bh[np][sel + 2]);
                mma_f16(acc[mt][nt], ah, bl[np][sel], bl[np][sel + 2]);
                mma_f16(acc[mt][nt], al, bh[np][sel], bh[np][sel + 2]);
            }
        }
    }

    // Epilogue: scale 1/8, add gumbel, store fp32 scores
#pragma unroll
    for (int mt = 0; mt < 4; mt++) {
        uint32_t m0 = bm * 128 + wm * 64 + mt * 16 + (lane >> 2);
#pragma unroll
        for (int nt = 0; nt < 4; nt++) {
            uint32_t col = bn * 128 + wn * 32 + nt * 8 + 2 * (lane & 3);
            uint32_t e0 = m0 * (uint32_t)NL + col;
            uint32_t e1 = (m0 + 8) * (uint32_t)NL + col;
            float2 v0, v1;
            v0.x = acc[mt][nt][0] * 0.125f + gumbel_at(e0);
            v0.y = acc[mt][nt][1] * 0.125f + gumbel_at(e0 + 1);
            v1.x = acc[mt][nt][2] * 0.125f + gumbel_at(e1);
            v1.y = acc[mt][nt][3] * 0.125f + gumbel_at(e1 + 1);
            *(float2*)(S + e0) = v0;
            *(float2*)(S + e1) = v1;
        }
    }
}

// ---------------------------------------------------------------------------
// Kernel B: in-place row softmax + fused fp16 conversion of P (scaled x1024)
// ---------------------------------------------------------------------------
__global__ __launch_bounds__(256)
void softmax_kernel(float* __restrict__ P)
{
    __shared__ float4 row4[NL / 4];
    __shared__ float red[8];
    const int r = blockIdx.x, t = threadIdx.x;
    float4* g = (float4*)(P + (size_t)r * NL);

    float mx = -INFINITY;
#pragma unroll
    for (int q = 0; q < 4; q++) {
        float4 v = g[t + 256 * q];
        row4[t + 256 * q] = v;
        mx = fmaxf(mx, fmaxf(fmaxf(v.x, v.y), fmaxf(v.z, v.w)));
    }
#pragma unroll
    for (int o = 16; o > 0; o >>= 1)
        mx = fmaxf(mx, __shfl_xor_sync(0xffffffffu, mx, o));
    if ((t & 31) == 0) red[t >> 5] = mx;
    __syncthreads();
    mx = red[0];
#pragma unroll
    for (int w = 1; w < 8; w++) mx = fmaxf(mx, red[w]);
    __syncthreads();

    float s = 0.0f;
#pragma unroll
    for (int q = 0; q < 4; q++) {
        float4 v = row4[t + 256 * q];
        v.x = __expf(v.x - mx); v.y = __expf(v.y - mx);
        v.z = __expf(v.z - mx); v.w = __expf(v.w - mx);
        row4[t + 256 * q] = v;
        s += (v.x + v.y) + (v.z + v.w);
    }
#pragma unroll
    for (int o = 16; o > 0; o >>= 1)
        s += __shfl_xor_sync(0xffffffffu, s, o);
    if ((t & 31) == 0) red[t >> 5] = s;
    __syncthreads();
    float tot = red[0];
#pragma unroll
    for (int w = 1; w < 8; w++) tot += red[w];
    float inv = 1.0f / tot;
    __syncthreads();

    uint2* ph = (uint2*)(g_Ph + (size_t)r * NL);
#pragma unroll
    for (int q = 0; q < 4; q++) {
        float4 v = row4[t + 256 * q];
        v.x *= inv; v.y *= inv; v.z *= inv; v.w *= inv;
        g[t + 256 * q] = v;
        __half2 h01 = __floats2half2_rn(v.x * PSCALE, v.y * PSCALE);
        __half2 h23 = __floats2half2_rn(v.z * PSCALE, v.w * PSCALE);
        ph[t + 256 * q] = make_uint2(*(uint32_t*)&h01, *(uint32_t*)&h23);
    }
}

// ---------------------------------------------------------------------------
// Kernel B2: transpose V to fp16:  V[k][n] -> V^T fp16 [n][k]
// ---------------------------------------------------------------------------
__global__ __launch_bounds__(256)
void vsplit_kernel(const float* __restrict__ V)
{
    __shared__ float tile[32][33];
    const int n0 = blockIdx.x * 32, k0 = blockIdx.y * 32;
    const int tx = threadIdx.x & 31, ty = threadIdx.x >> 5;
#pragma unroll
    for (int i = 0; i < 32; i += 8)
        tile[ty + i][tx] = V[(size_t)(k0 + ty + i) * NC + n0 + tx];
    __syncthreads();
#pragma unroll
    for (int i = 0; i < 32; i += 8) {
        float f = tile[tx][ty + i];
        g_VhT[(size_t)(n0 + ty + i) * NL + k0 + tx] = __float2half_rn(f);
    }
}

// ---------------------------------------------------------------------------
// Kernel C: out = P @ V, fp16 mma.sync (Ph*Vh), fp32 accum.
// CTA tile 64x128, 128 threads (4 warps, 1x4), warp 64x32, BK=32, 3 stages.
// 4 CTAs/SM -> desynchronized barriers.
// ---------------------------------------------------------------------------
#define SP 40
#define P_ARR (64 * SP * 2)            // 5120 B
#define V_ARR (128 * SP * 2)           // 10240 B
#define STAGE_BYTES (P_ARR + V_ARR)    // 15360 B
#define NSTAGE 3
#define PV_SMEM (NSTAGE * STAGE_BYTES) // 46080 B

__global__ __launch_bounds__(128, 4)
void pv_kernel(float* __restrict__ O)
{
    extern __shared__ __align__(16) char dsm[];
    const uint32_t sbase = smem_to_u32(dsm);

    const int tid = threadIdx.x;
    const int lane = tid & 31, wn = tid >> 5;        // 4 warps across n
    const int bn = blockIdx.x, bm = blockIdx.y;      // bn: 8, bm: 256

    const __half* srcP = g_Ph  + (size_t)(bm * 64) * NL;
    const __half* srcV = g_VhT + (size_t)(bn * 128) * NL;

    float acc[4][4][4];
#pragma unroll
    for (int i = 0; i < 4; i++)
#pragma unroll
        for (int j = 0; j < 4; j++)
#pragma unroll
            for (int q = 0; q < 4; q++) acc[i][j][q] = 0.0f;

    const int lrow = (lane & 7) + ((lane >> 3) & 1) * 8;
    const int lcol8 = (lane >> 4) * 8;

    auto load_stage = [&](int st, int k0) {
        uint32_t stb = sbase + st * STAGE_BYTES;
        // P: 64 rows x 4 kc = 256 slots, 2 per thread
#pragma unroll
        for (int u = 0; u < 2; u++) {
            int idx = tid + 128 * u;
            int row = idx >> 2, kc = idx & 3;
            cpa16(stb + (row * SP + kc * 8) * 2, srcP + (size_t)row * NL + k0 + kc * 8);
        }
        // V: 128 rows x 4 kc = 512 slots, 4 per thread
#pragma unroll
        for (int u = 0; u < 4; u++) {
            int idx = tid + 128 * u;
            int row = idx >> 2, kc = idx & 3;
            cpa16(stb + P_ARR + (row * SP + kc * 8) * 2, srcV + (size_t)row * NL + k0 + kc * 8);
        }
    };

    load_stage(0, 0);  CP_COMMIT();
    load_stage(1, 32); CP_COMMIT();

    const int NCH = NL / 32;   // 128 chunks
    for (int c = 0; c < NCH; c++) {
        CP_WAIT1();
        __syncthreads();
        if (c + 2 < NCH) load_stage((c + 2) % NSTAGE, (c + 2) * 32);
        CP_COMMIT();

        const uint32_t stb = sbase + (c % NSTAGE) * STAGE_BYTES;
        const uint32_t uPh = stb, uVh = stb + P_ARR;

#pragma unroll
        for (int kk = 0; kk < 32; kk += 16) {
            const uint32_t aoff = ((lrow) * SP + kk + lcol8) * 2;
            const uint32_t boff = ((wn * 32 + lrow) * SP + kk + lcol8) * 2;
            uint32_t ah[4][4];
#pragma unroll
            for (int mt = 0; mt < 4; mt++)
                ldsm4(ah[mt], uPh + aoff + mt * (16 * SP * 2));
            uint32_t bh[2][4];
#pragma unroll
            for (int np = 0; np < 2; np++)
                ldsm4(bh[np], uVh + boff + np * (16 * SP * 2));
#pragma unroll
            for (int mt = 0; mt < 4; mt++)
#pragma unroll
                for (int nt = 0; nt < 4; nt++) {
                    const int np = nt >> 1, sel = nt & 1;
                    mma_f16(acc[mt][nt], ah[mt], bh[np][sel], bh[np][sel + 2]);
                }
        }
    }

    // Epilogue (undo the 1024x P scaling)
#pragma unroll
    for (int mt = 0; mt < 4; mt++) {
        int m = bm * 64 + mt * 16 + (lane >> 2);
#pragma unroll
        for (int nt = 0; nt < 4; nt++) {
            int col = bn * 128 + wn * 32 + nt * 8 + 2 * (lane & 3);
            float2 v0 = make_float2(acc[mt][nt][0] * INV_PSCALE,
                                    acc[mt][nt][1] * INV_PSCALE);
            float2 v1 = make_float2(acc[mt][nt][2] * INV_PSCALE,
                                    acc[mt][nt][3] * INV_PSCALE);
            *(float2*)(O + (size_t)m * NC + col)       = v0;
            *(float2*)(O + (size_t)(m + 8) * NC + col) = v1;
        }
    }
}

// ---------------------------------------------------------------------------
// Launch
// ---------------------------------------------------------------------------
extern "C" void kernel_launch(void* const* d_in, const int* in_sizes, int n_in,
                              void* d_out, int out_size) {
    const float* Q  = (const float*)d_in[0];   // [16384, 64]
    const float* Km = (const float*)d_in[1];   // [4096, 64]
    const float* V  = (const float*)d_in[2];   // [4096, 1024]
    float* out = (float*)d_out;                // [16384, 1024]
    float* P   = out + OUT_ELEMS;              // [16384, 4096] p_attn

    static bool attr_done = false;
    if (!attr_done) {
        cudaFuncSetAttribute(pv_kernel, cudaFuncAttributeMaxDynamicSharedMemorySize,
                             PV_SMEM);
        cudaFuncSetAttribute(score_kernel, cudaFuncAttributeMaxDynamicSharedMemorySize,
                             SC_SMEM);
        attr_done = true;
    }

    dim3 gA(NL / 128, NG / 128);               // 32 x 128
    score_kernel<<<gA, 256, SC_SMEM>>>(Q, Km, P);

    vsplit_kernel<<<dim3(NC / 32, NL / 32), 256>>>(V);

    softmax_kernel<<<NG, 256>>>(P);

    dim3 gC(NC / 128, NG / 64);                // 8 x 256
    pv_kernel<<<gC, 128, PV_SMEM>>>(out);
}